// round 5
// baseline (speedup 1.0000x reference)
#include <cuda_runtime.h>
#include <stdint.h>

#define NN 100000
#define DD 64
#define EE 1200000
#define AL 0.25f
#define SCAN_B 1024
#define NBLK ((NN + SCAN_B - 1) / SCAN_B)   // 98

// ---------------- scratch (static __device__, no allocs) ----------------
__device__ __align__(16) float g_deg[NN];
__device__ __align__(16) float g_dinv[NN];
__device__ __align__(16) int2  g_pair[EE];   // (row, norm bits) grouped by target col
__device__ __align__(16) int   g_cnt[NN];
__device__ __align__(16) int   g_off[NN + 1];
__device__ __align__(16) int   g_cur[NN];
__device__ int g_blk_status[NBLK];   // 0=none, 1=aggregate ready, 2=prefix ready
__device__ int g_blk_agg[NBLK];
__device__ int g_blk_pref[NBLK];     // inclusive prefix
__device__ int g_idx_is32;
__device__ int g_mask_is8;
__device__ __align__(16) float g_hbuf[2][NN * DD];

// ---------------- kernels ----------------

// zero deg/cnt/status; block 0 additionally does a sampled dtype probe.
// eidx viewed as int32: for int64 storage (values < 2^31) every odd word is 0;
// for int32 storage odd words are node indices. mask viewed as bytes: for
// int32-bool storage bytes at i%4!=0 are 0. 16K samples each; all reads
// in-bounds under either interpretation.
__global__ void k_zero_probe(const int* __restrict__ ei32,
                             const unsigned char* __restrict__ m8) {
    int i = blockIdx.x * blockDim.x + threadIdx.x;
    if (i < NN) { g_deg[i] = 0.f; g_cnt[i] = 0; }
    if (i < NBLK) g_blk_status[i] = 0;
    if (blockIdx.x == 0) {
        if (threadIdx.x == 0) { g_idx_is32 = 0; g_mask_is8 = 0; }
        __syncthreads();
        int any_odd = 0, any_off = 0;
        for (int k = 0; k < 64; k++) {
            int s = threadIdx.x + k * blockDim.x;   // s in [0, 16384)
            any_odd |= (ei32[2 * s + 1] != 0);
            unsigned char b = m8[s];
            if (s & 3) any_off |= (b != 0);
        }
        if (__syncthreads_or(any_odd)) { if (threadIdx.x == 0) g_idx_is32 = 1; }
        if (__syncthreads_or(any_off)) { if (threadIdx.x == 0) g_mask_is8 = 1; }
    }
}

__device__ __forceinline__ void decode_edge(const float* __restrict__ attr,
                                            const int* __restrict__ ei32,
                                            const unsigned char* __restrict__ m8,
                                            int e, int& r, int& c, float& w) {
    bool mk = g_mask_is8 ? (m8[e] != 0)
                         : (reinterpret_cast<const int*>(m8)[e] != 0);
    if (g_idx_is32) { r = ei32[e];        c = ei32[EE + e]; }
    else            { r = ei32[2LL * e];  c = ei32[2LL * (EE + e)]; }
    w = mk ? __ldg(attr + e) : 0.f;
    if ((unsigned)r >= NN || (unsigned)c >= NN) w = 0.f;
}

// pure decode + atomics: weighted degree and kept-edge count at target col
__global__ void k_prep(const float* __restrict__ attr,
                       const int* __restrict__ ei32,
                       const unsigned char* __restrict__ m8) {
    int e = blockIdx.x * blockDim.x + threadIdx.x;
    if (e >= EE) return;
    int r, c; float w;
    decode_edge(attr, ei32, m8, e, r, c, w);
    if (w > 0.f) {
        atomicAdd(&g_deg[c], w);
        atomicAdd(&g_cnt[c], 1);
    }
}

// fused: dinv + full exclusive scan of cnt (decoupled lookback) + cursor init
__global__ void __launch_bounds__(SCAN_B) k_scan() {
    __shared__ int s_wsum[32];
    __shared__ int s_bexcl;
    int b = blockIdx.x;
    int i = b * SCAN_B + threadIdx.x;
    int lane = threadIdx.x & 31;
    int wid = threadIdx.x >> 5;

    if (i < NN) {
        float d = g_deg[i];
        g_dinv[i] = (d > 0.f) ? rsqrtf(d) : 0.f;
    }
    int v = (i < NN) ? g_cnt[i] : 0;

    // warp inclusive scan
    int x = v;
    #pragma unroll
    for (int d = 1; d < 32; d <<= 1) {
        int t = __shfl_up_sync(0xffffffffu, x, d);
        if (lane >= d) x += t;
    }
    if (lane == 31) s_wsum[wid] = x;
    __syncthreads();
    if (wid == 0) {
        int y = s_wsum[lane];
        #pragma unroll
        for (int d = 1; d < 32; d <<= 1) {
            int t = __shfl_up_sync(0xffffffffu, y, d);
            if (lane >= d) y += t;
        }
        s_wsum[lane] = y;   // inclusive warp-sum prefix
    }
    __syncthreads();
    int incl = x + (wid > 0 ? s_wsum[wid - 1] : 0);   // inclusive within block
    int agg = s_wsum[31];                             // block total

    // publish aggregate, then look back for exclusive block prefix
    if (threadIdx.x == 0) {
        g_blk_agg[b] = agg;
        __threadfence();
        atomicExch(&g_blk_status[b], 1);
        int excl = 0;
        int p = b - 1;
        while (p >= 0) {
            int s;
            do { s = atomicAdd(&g_blk_status[p], 0); } while (s == 0);
            if (s == 2) { excl += *((volatile int*)&g_blk_pref[p]); break; }
            excl += *((volatile int*)&g_blk_agg[p]);
            p--;
        }
        g_blk_pref[b] = excl + agg;
        __threadfence();
        atomicExch(&g_blk_status[b], 2);
        s_bexcl = excl;
    }
    __syncthreads();
    int bexcl = s_bexcl;
    if (i < NN) {
        int o = bexcl + incl - v;   // global exclusive prefix
        g_off[i] = o;
        g_cur[i] = o;
        if (i == NN - 1) g_off[NN] = bexcl + incl;
    }
}

// fill CSR: re-decode inputs, (row, norm) pairs grouped by target col
// (norm may be 0 if dinv[row]==0 -- contributes nothing)
__global__ void k_fill(const float* __restrict__ attr,
                       const int* __restrict__ ei32,
                       const unsigned char* __restrict__ m8) {
    int e = blockIdx.x * blockDim.x + threadIdx.x;
    if (e >= EE) return;
    int r, c; float w;
    decode_edge(attr, ei32, m8, e, r, c, w);
    if (w <= 0.f) return;
    float nrm = w * g_dinv[r] * g_dinv[c];
    int pos = atomicAdd(&g_cur[c], 1);
    g_pair[pos] = make_int2(r, __float_as_int(nrm));
}

// pull one layer: 16 threads/node, register accumulation, unroll x2
__global__ void k_gather(const float* __restrict__ hin, float* __restrict__ hout) {
    int gid = blockIdx.x * blockDim.x + threadIdx.x;
    int node = gid >> 4;
    if (node >= NN) return;
    int lane = gid & 15;
    int j = g_off[node];
    int end = g_off[node + 1];
    float4 acc = make_float4(0.f, 0.f, 0.f, 0.f);
    for (; j + 1 < end; j += 2) {
        int2 p0 = __ldg(&g_pair[j]);
        int2 p1 = __ldg(&g_pair[j + 1]);
        float4 v0 = __ldg(reinterpret_cast<const float4*>(hin + (size_t)p0.x * DD) + lane);
        float4 v1 = __ldg(reinterpret_cast<const float4*>(hin + (size_t)p1.x * DD) + lane);
        float n0 = __int_as_float(p0.y), n1 = __int_as_float(p1.y);
        acc.x = fmaf(n0, v0.x, acc.x); acc.y = fmaf(n0, v0.y, acc.y);
        acc.z = fmaf(n0, v0.z, acc.z); acc.w = fmaf(n0, v0.w, acc.w);
        acc.x = fmaf(n1, v1.x, acc.x); acc.y = fmaf(n1, v1.y, acc.y);
        acc.z = fmaf(n1, v1.z, acc.z); acc.w = fmaf(n1, v1.w, acc.w);
    }
    if (j < end) {
        int2 p0 = __ldg(&g_pair[j]);
        float4 v0 = __ldg(reinterpret_cast<const float4*>(hin + (size_t)p0.x * DD) + lane);
        float n0 = __int_as_float(p0.y);
        acc.x = fmaf(n0, v0.x, acc.x); acc.y = fmaf(n0, v0.y, acc.y);
        acc.z = fmaf(n0, v0.z, acc.z); acc.w = fmaf(n0, v0.w, acc.w);
    }
    reinterpret_cast<float4*>(hout + (size_t)node * DD)[lane] = acc;
}

// last layer fused with epilogue: out = AL*(x + h1 + h2 + acc), h2 == hin
__global__ void k_gather_last(const float* __restrict__ hin,
                              const float* __restrict__ x,
                              const float* __restrict__ h1,
                              float* __restrict__ out) {
    int gid = blockIdx.x * blockDim.x + threadIdx.x;
    int node = gid >> 4;
    if (node >= NN) return;
    int lane = gid & 15;
    int j = g_off[node];
    int end = g_off[node + 1];
    float4 acc = make_float4(0.f, 0.f, 0.f, 0.f);
    for (; j + 1 < end; j += 2) {
        int2 p0 = __ldg(&g_pair[j]);
        int2 p1 = __ldg(&g_pair[j + 1]);
        float4 v0 = __ldg(reinterpret_cast<const float4*>(hin + (size_t)p0.x * DD) + lane);
        float4 v1 = __ldg(reinterpret_cast<const float4*>(hin + (size_t)p1.x * DD) + lane);
        float n0 = __int_as_float(p0.y), n1 = __int_as_float(p1.y);
        acc.x = fmaf(n0, v0.x, acc.x); acc.y = fmaf(n0, v0.y, acc.y);
        acc.z = fmaf(n0, v0.z, acc.z); acc.w = fmaf(n0, v0.w, acc.w);
        acc.x = fmaf(n1, v1.x, acc.x); acc.y = fmaf(n1, v1.y, acc.y);
        acc.z = fmaf(n1, v1.z, acc.z); acc.w = fmaf(n1, v1.w, acc.w);
    }
    if (j < end) {
        int2 p0 = __ldg(&g_pair[j]);
        float4 v0 = __ldg(reinterpret_cast<const float4*>(hin + (size_t)p0.x * DD) + lane);
        float n0 = __int_as_float(p0.y);
        acc.x = fmaf(n0, v0.x, acc.x); acc.y = fmaf(n0, v0.y, acc.y);
        acc.z = fmaf(n0, v0.z, acc.z); acc.w = fmaf(n0, v0.w, acc.w);
    }
    size_t base = (size_t)node * DD;
    float4 a = __ldg(reinterpret_cast<const float4*>(x + base) + lane);
    float4 b = __ldg(reinterpret_cast<const float4*>(h1 + base) + lane);
    float4 c = __ldg(reinterpret_cast<const float4*>(hin + base) + lane);
    float4 o;
    o.x = AL * (a.x + b.x + c.x + acc.x);
    o.y = AL * (a.y + b.y + c.y + acc.y);
    o.z = AL * (a.z + b.z + c.z + acc.z);
    o.w = AL * (a.w + b.w + c.w + acc.w);
    reinterpret_cast<float4*>(out + base)[lane] = o;
}

// ---------------- launch ----------------
extern "C" void kernel_launch(void* const* d_in, const int* in_sizes, int n_in,
                              void* d_out, int out_size) {
    const float* x = (const float*)d_in[0];
    const float* attr = (const float*)d_in[1];
    const int* ei32 = (const int*)d_in[2];
    const unsigned char* m8 = (const unsigned char*)d_in[3];
    float* out = (float*)d_out;

    void* hbp = nullptr;
    cudaGetSymbolAddress(&hbp, g_hbuf);
    float* h1 = (float*)hbp;
    float* h2 = h1 + (size_t)NN * DD;

    const int B = 256;
    const int gridE = (EE + B - 1) / B;
    const int gridN = (NN + B - 1) / B;
    const int gridGather = (NN * 16 + B - 1) / B;

    k_zero_probe<<<gridN, B>>>(ei32, m8);
    k_prep<<<gridE, B>>>(attr, ei32, m8);
    k_scan<<<NBLK, SCAN_B>>>();
    k_fill<<<gridE, B>>>(attr, ei32, m8);

    k_gather<<<gridGather, B>>>(x,  h1);
    k_gather<<<gridGather, B>>>(h1, h2);
    k_gather_last<<<gridGather, B>>>(h2, x, h1, out);
}

// round 6
// speedup vs baseline: 1.0552x; 1.0552x over previous
#include <cuda_runtime.h>
#include <stdint.h>

#define NN 100000
#define DD 64
#define EE 1200000
#define AL 0.25f
#define SCAN_B 1024
#define NBLK ((NN + SCAN_B - 1) / SCAN_B)   // 98

// ---------------- scratch (static __device__, zero-init at load) ----------------
__device__ __align__(16) float g_deg[NN];       // self-cleaned by k_scan
__device__ __align__(16) float g_dinv[NN];
__device__ __align__(16) float g_w[EE];
__device__ __align__(16) int   g_row0[EE];
__device__ __align__(16) int   g_col0[EE];
__device__ __align__(16) int2  g_pair[EE];      // (row, norm bits) grouped by target col
__device__ __align__(16) int   g_cnt[NN];       // self-cleaned by k_scan
__device__ __align__(16) int   g_off[NN + 1];
__device__ __align__(16) int   g_cur[NN];
__device__ int g_blk_status[NBLK];   // zeroed by k_probe each call
__device__ int g_blk_agg[NBLK];
__device__ int g_blk_pref[NBLK];
__device__ int g_idx_is32;
__device__ int g_mask_is8;
__device__ __align__(16) float g_hbuf[2][NN * DD];

// ---------------- kernels ----------------

// One block: zero lookback status + sampled dtype probe.
// eidx viewed as int32: for int64 storage (values < 2^31) every odd word is 0;
// for int32 storage odd words are real node indices. mask viewed as bytes: for
// int32-bool storage every byte at i%4!=0 is 0. 16K samples each -> detection
// certain for real data; all reads in-bounds under either interpretation.
__global__ void __launch_bounds__(1024) k_probe(const int* __restrict__ ei32,
                                                const unsigned char* __restrict__ m8) {
    if (threadIdx.x < NBLK) g_blk_status[threadIdx.x] = 0;
    if (threadIdx.x == 0) { g_idx_is32 = 0; g_mask_is8 = 0; }
    __syncthreads();
    int any_odd = 0, any_off = 0;
    #pragma unroll
    for (int k = 0; k < 16; k++) {
        int s = threadIdx.x + k * 1024;         // s in [0, 16384)
        any_odd |= (ei32[2 * s + 1] != 0);
        unsigned char b = m8[s];
        if (s & 3) any_off |= (b != 0);
    }
    if (__syncthreads_or(any_odd)) { if (threadIdx.x == 0) g_idx_is32 = 1; }
    if (__syncthreads_or(any_off)) { if (threadIdx.x == 0) g_mask_is8 = 1; }
}

// decode once, materialize (w,row,col), accumulate deg + cnt at target col
__global__ void k_prep(const float* __restrict__ attr,
                       const int* __restrict__ ei32,
                       const unsigned char* __restrict__ m8) {
    int e = blockIdx.x * blockDim.x + threadIdx.x;
    if (e >= EE) return;
    bool mk = g_mask_is8 ? (m8[e] != 0)
                         : (reinterpret_cast<const int*>(m8)[e] != 0);
    int r, c;
    if (g_idx_is32) { r = ei32[e];        c = ei32[EE + e]; }
    else            { r = ei32[2LL * e];  c = ei32[2LL * (EE + e)]; }
    float w = mk ? __ldg(attr + e) : 0.f;
    if ((unsigned)r >= NN || (unsigned)c >= NN) w = 0.f;
    g_w[e] = w;
    g_row0[e] = r;
    g_col0[e] = c;
    if (w > 0.f) {
        atomicAdd(&g_deg[c], w);
        atomicAdd(&g_cnt[c], 1);
    }
}

// fused: dinv + exclusive scan of cnt (decoupled lookback) + cursor init
// + self-clean deg/cnt for the next graph replay
__global__ void __launch_bounds__(SCAN_B) k_scan() {
    __shared__ int s_wsum[32];
    __shared__ int s_bexcl;
    int b = blockIdx.x;
    int i = b * SCAN_B + threadIdx.x;
    int lane = threadIdx.x & 31;
    int wid = threadIdx.x >> 5;

    int v = 0;
    if (i < NN) {
        float d = g_deg[i];
        g_dinv[i] = (d > 0.f) ? rsqrtf(d) : 0.f;
        g_deg[i] = 0.f;              // self-clean
        v = g_cnt[i];
        g_cnt[i] = 0;                // self-clean
    }

    // warp inclusive scan
    int x = v;
    #pragma unroll
    for (int d = 1; d < 32; d <<= 1) {
        int t = __shfl_up_sync(0xffffffffu, x, d);
        if (lane >= d) x += t;
    }
    if (lane == 31) s_wsum[wid] = x;
    __syncthreads();
    if (wid == 0) {
        int y = s_wsum[lane];
        #pragma unroll
        for (int d = 1; d < 32; d <<= 1) {
            int t = __shfl_up_sync(0xffffffffu, y, d);
            if (lane >= d) y += t;
        }
        s_wsum[lane] = y;
    }
    __syncthreads();
    int incl = x + (wid > 0 ? s_wsum[wid - 1] : 0);
    int agg = s_wsum[31];

    if (threadIdx.x == 0) {
        g_blk_agg[b] = agg;
        __threadfence();
        atomicExch(&g_blk_status[b], 1);
        int excl = 0;
        int p = b - 1;
        while (p >= 0) {
            int s;
            do { s = atomicAdd(&g_blk_status[p], 0); } while (s == 0);
            if (s == 2) { excl += *((volatile int*)&g_blk_pref[p]); break; }
            excl += *((volatile int*)&g_blk_agg[p]);
            p--;
        }
        g_blk_pref[b] = excl + agg;
        __threadfence();
        atomicExch(&g_blk_status[b], 2);
        s_bexcl = excl;
    }
    __syncthreads();
    int bexcl = s_bexcl;
    if (i < NN) {
        int o = bexcl + incl - v;
        g_off[i] = o;
        g_cur[i] = o;
        if (i == NN - 1) g_off[NN] = bexcl + incl;
    }
}

// fill CSR from materialized arrays (norm may be 0 if dinv[row]==0; harmless)
__global__ void k_fill() {
    int e = blockIdx.x * blockDim.x + threadIdx.x;
    if (e >= EE) return;
    float w = g_w[e];
    if (w <= 0.f) return;
    int r = g_row0[e];
    int c = g_col0[e];
    float nrm = w * g_dinv[r] * g_dinv[c];
    int pos = atomicAdd(&g_cur[c], 1);
    g_pair[pos] = make_int2(r, __float_as_int(nrm));
}

// pull one layer: 16 threads/node, register accumulation, unroll x2
__global__ void k_gather(const float* __restrict__ hin, float* __restrict__ hout) {
    int gid = blockIdx.x * blockDim.x + threadIdx.x;
    int node = gid >> 4;
    if (node >= NN) return;
    int lane = gid & 15;
    int j = g_off[node];
    int end = g_off[node + 1];
    float4 acc = make_float4(0.f, 0.f, 0.f, 0.f);
    for (; j + 1 < end; j += 2) {
        int2 p0 = __ldg(&g_pair[j]);
        int2 p1 = __ldg(&g_pair[j + 1]);
        float4 v0 = __ldg(reinterpret_cast<const float4*>(hin + (size_t)p0.x * DD) + lane);
        float4 v1 = __ldg(reinterpret_cast<const float4*>(hin + (size_t)p1.x * DD) + lane);
        float n0 = __int_as_float(p0.y), n1 = __int_as_float(p1.y);
        acc.x = fmaf(n0, v0.x, acc.x); acc.y = fmaf(n0, v0.y, acc.y);
        acc.z = fmaf(n0, v0.z, acc.z); acc.w = fmaf(n0, v0.w, acc.w);
        acc.x = fmaf(n1, v1.x, acc.x); acc.y = fmaf(n1, v1.y, acc.y);
        acc.z = fmaf(n1, v1.z, acc.z); acc.w = fmaf(n1, v1.w, acc.w);
    }
    if (j < end) {
        int2 p0 = __ldg(&g_pair[j]);
        float4 v0 = __ldg(reinterpret_cast<const float4*>(hin + (size_t)p0.x * DD) + lane);
        float n0 = __int_as_float(p0.y);
        acc.x = fmaf(n0, v0.x, acc.x); acc.y = fmaf(n0, v0.y, acc.y);
        acc.z = fmaf(n0, v0.z, acc.z); acc.w = fmaf(n0, v0.w, acc.w);
    }
    reinterpret_cast<float4*>(hout + (size_t)node * DD)[lane] = acc;
}

// last layer fused with epilogue: out = AL*(x + h1 + h2 + acc), h2 == hin
__global__ void k_gather_last(const float* __restrict__ hin,
                              const float* __restrict__ x,
                              const float* __restrict__ h1,
                              float* __restrict__ out) {
    int gid = blockIdx.x * blockDim.x + threadIdx.x;
    int node = gid >> 4;
    if (node >= NN) return;
    int lane = gid & 15;
    int j = g_off[node];
    int end = g_off[node + 1];
    float4 acc = make_float4(0.f, 0.f, 0.f, 0.f);
    for (; j + 1 < end; j += 2) {
        int2 p0 = __ldg(&g_pair[j]);
        int2 p1 = __ldg(&g_pair[j + 1]);
        float4 v0 = __ldg(reinterpret_cast<const float4*>(hin + (size_t)p0.x * DD) + lane);
        float4 v1 = __ldg(reinterpret_cast<const float4*>(hin + (size_t)p1.x * DD) + lane);
        float n0 = __int_as_float(p0.y), n1 = __int_as_float(p1.y);
        acc.x = fmaf(n0, v0.x, acc.x); acc.y = fmaf(n0, v0.y, acc.y);
        acc.z = fmaf(n0, v0.z, acc.z); acc.w = fmaf(n0, v0.w, acc.w);
        acc.x = fmaf(n1, v1.x, acc.x); acc.y = fmaf(n1, v1.y, acc.y);
        acc.z = fmaf(n1, v1.z, acc.z); acc.w = fmaf(n1, v1.w, acc.w);
    }
    if (j < end) {
        int2 p0 = __ldg(&g_pair[j]);
        float4 v0 = __ldg(reinterpret_cast<const float4*>(hin + (size_t)p0.x * DD) + lane);
        float n0 = __int_as_float(p0.y);
        acc.x = fmaf(n0, v0.x, acc.x); acc.y = fmaf(n0, v0.y, acc.y);
        acc.z = fmaf(n0, v0.z, acc.z); acc.w = fmaf(n0, v0.w, acc.w);
    }
    size_t base = (size_t)node * DD;
    float4 a = __ldg(reinterpret_cast<const float4*>(x + base) + lane);
    float4 b = __ldg(reinterpret_cast<const float4*>(h1 + base) + lane);
    float4 c = __ldg(reinterpret_cast<const float4*>(hin + base) + lane);
    float4 o;
    o.x = AL * (a.x + b.x + c.x + acc.x);
    o.y = AL * (a.y + b.y + c.y + acc.y);
    o.z = AL * (a.z + b.z + c.z + acc.z);
    o.w = AL * (a.w + b.w + c.w + acc.w);
    reinterpret_cast<float4*>(out + base)[lane] = o;
}

// ---------------- launch ----------------
extern "C" void kernel_launch(void* const* d_in, const int* in_sizes, int n_in,
                              void* d_out, int out_size) {
    const float* x = (const float*)d_in[0];
    const float* attr = (const float*)d_in[1];
    const int* ei32 = (const int*)d_in[2];
    const unsigned char* m8 = (const unsigned char*)d_in[3];
    float* out = (float*)d_out;

    void* hbp = nullptr;
    cudaGetSymbolAddress(&hbp, g_hbuf);
    float* h1 = (float*)hbp;
    float* h2 = h1 + (size_t)NN * DD;

    const int B = 256;
    const int gridE = (EE + B - 1) / B;
    const int gridGather = (NN * 16 + B - 1) / B;

    k_probe<<<1, 1024>>>(ei32, m8);
    k_prep<<<gridE, B>>>(attr, ei32, m8);
    k_scan<<<NBLK, SCAN_B>>>();
    k_fill<<<gridE, B>>>();

    k_gather<<<gridGather, B>>>(x,  h1);
    k_gather<<<gridGather, B>>>(h1, h2);
    k_gather_last<<<gridGather, B>>>(h2, x, h1, out);
}

// round 7
// speedup vs baseline: 1.0743x; 1.0181x over previous
#include <cuda_runtime.h>
#include <stdint.h>

#define NN 100000
#define DD 64
#define EE 1200000
#define AL 0.25f
#define SCAN_B 1024
#define NBLK ((NN + SCAN_B - 1) / SCAN_B)   // 98
#define FIX (16777216.0f)                   // 2^24 fixed-point scale for degree

// ---------------- scratch (static __device__, zero-init at load) ----------------
__device__ unsigned long long g_cntdeg[NN];     // [63:40]=count, [39:0]=deg*2^24 ; self-cleaned
__device__ __align__(16) float g_dinv[NN];
__device__ __align__(16) float g_w[EE];
__device__ __align__(16) int   g_row0[EE];
__device__ __align__(16) int   g_col0[EE];
__device__ unsigned short     g_rank[EE];
__device__ __align__(16) int2  g_pair[EE];      // (row, norm bits) grouped by target col
__device__ __align__(16) int   g_off[NN + 1];
__device__ int g_blk_status[NBLK];   // zeroed by k_probe each call
__device__ int g_blk_agg[NBLK];
__device__ int g_blk_pref[NBLK];
__device__ int g_idx_is32;
__device__ int g_mask_is8;
__device__ __align__(16) float g_hbuf[2][NN * DD];

// ---------------- kernels ----------------

// One block: zero lookback status + sampled dtype probe.
// eidx viewed as int32: for int64 storage (values < 2^31) every odd word is 0;
// for int32 storage odd words are real node indices. mask viewed as bytes: for
// int32-bool storage every byte at i%4!=0 is 0. 16K samples each; all reads
// in-bounds under either interpretation.
__global__ void __launch_bounds__(1024) k_probe(const int* __restrict__ ei32,
                                                const unsigned char* __restrict__ m8) {
    if (threadIdx.x < NBLK) g_blk_status[threadIdx.x] = 0;
    if (threadIdx.x == 0) { g_idx_is32 = 0; g_mask_is8 = 0; }
    __syncthreads();
    int any_odd = 0, any_off = 0;
    #pragma unroll
    for (int k = 0; k < 16; k++) {
        int s = threadIdx.x + k * 1024;         // s in [0, 16384)
        any_odd |= (ei32[2 * s + 1] != 0);
        unsigned char b = m8[s];
        if (s & 3) any_off |= (b != 0);
    }
    if (__syncthreads_or(any_odd)) { if (threadIdx.x == 0) g_idx_is32 = 1; }
    if (__syncthreads_or(any_off)) { if (threadIdx.x == 0) g_mask_is8 = 1; }
}

// decode once, materialize (w,row,col,rank); ONE packed 64-bit atomic yields
// both the weighted-degree accumulation and this edge's rank at its target.
__global__ void k_prep(const float* __restrict__ attr,
                       const int* __restrict__ ei32,
                       const unsigned char* __restrict__ m8) {
    int e = blockIdx.x * blockDim.x + threadIdx.x;
    if (e >= EE) return;
    bool mk = g_mask_is8 ? (m8[e] != 0)
                         : (reinterpret_cast<const int*>(m8)[e] != 0);
    int r, c;
    if (g_idx_is32) { r = ei32[e];        c = ei32[EE + e]; }
    else            { r = ei32[2LL * e];  c = ei32[2LL * (EE + e)]; }
    float w = mk ? __ldg(attr + e) : 0.f;
    if ((unsigned)r >= NN || (unsigned)c >= NN) w = 0.f;
    g_w[e] = w;
    g_row0[e] = r;
    g_col0[e] = c;
    unsigned short rk = 0;
    if (w > 0.f) {
        unsigned long long inc =
            (1ull << 40) | (unsigned long long)(w * FIX);
        unsigned long long old = atomicAdd(&g_cntdeg[c], inc);
        rk = (unsigned short)(old >> 40);
    }
    g_rank[e] = rk;
}

// fused: unpack (cnt,deg) -> dinv + exclusive scan of cnt (decoupled lookback)
// + self-clean cntdeg for the next graph replay
__global__ void __launch_bounds__(SCAN_B) k_scan() {
    __shared__ int s_wsum[32];
    __shared__ int s_bexcl;
    int b = blockIdx.x;
    int i = b * SCAN_B + threadIdx.x;
    int lane = threadIdx.x & 31;
    int wid = threadIdx.x >> 5;

    int v = 0;
    if (i < NN) {
        unsigned long long pk = g_cntdeg[i];
        g_cntdeg[i] = 0ull;          // self-clean
        v = (int)(pk >> 40);
        float d = (float)(pk & ((1ull << 40) - 1ull)) * (1.0f / FIX);
        g_dinv[i] = (d > 0.f) ? rsqrtf(d) : 0.f;
    }

    // warp inclusive scan
    int x = v;
    #pragma unroll
    for (int d = 1; d < 32; d <<= 1) {
        int t = __shfl_up_sync(0xffffffffu, x, d);
        if (lane >= d) x += t;
    }
    if (lane == 31) s_wsum[wid] = x;
    __syncthreads();
    if (wid == 0) {
        int y = s_wsum[lane];
        #pragma unroll
        for (int d = 1; d < 32; d <<= 1) {
            int t = __shfl_up_sync(0xffffffffu, y, d);
            if (lane >= d) y += t;
        }
        s_wsum[lane] = y;
    }
    __syncthreads();
    int incl = x + (wid > 0 ? s_wsum[wid - 1] : 0);
    int agg = s_wsum[31];

    if (threadIdx.x == 0) {
        g_blk_agg[b] = agg;
        __threadfence();
        atomicExch(&g_blk_status[b], 1);
        int excl = 0;
        int p = b - 1;
        while (p >= 0) {
            int s;
            do { s = atomicAdd(&g_blk_status[p], 0); } while (s == 0);
            if (s == 2) { excl += *((volatile int*)&g_blk_pref[p]); break; }
            excl += *((volatile int*)&g_blk_agg[p]);
            p--;
        }
        g_blk_pref[b] = excl + agg;
        __threadfence();
        atomicExch(&g_blk_status[b], 2);
        s_bexcl = excl;
    }
    __syncthreads();
    int bexcl = s_bexcl;
    if (i < NN) {
        g_off[i] = bexcl + incl - v;
        if (i == NN - 1) g_off[NN] = bexcl + incl;
    }
}

// fill CSR: NO atomics — position = off[col] + rank (norm may be 0 if
// dinv[row]==0; contributes nothing)
__global__ void k_fill() {
    int e = blockIdx.x * blockDim.x + threadIdx.x;
    if (e >= EE) return;
    float w = g_w[e];
    if (w <= 0.f) return;
    int r = g_row0[e];
    int c = g_col0[e];
    float nrm = w * g_dinv[r] * g_dinv[c];
    int pos = g_off[c] + (int)g_rank[e];
    g_pair[pos] = make_int2(r, __float_as_int(nrm));
}

// pull one layer: 16 threads/node, register accumulation, unroll x2
__global__ void k_gather(const float* __restrict__ hin, float* __restrict__ hout) {
    int gid = blockIdx.x * blockDim.x + threadIdx.x;
    int node = gid >> 4;
    if (node >= NN) return;
    int lane = gid & 15;
    int j = g_off[node];
    int end = g_off[node + 1];
    float4 acc = make_float4(0.f, 0.f, 0.f, 0.f);
    for (; j + 1 < end; j += 2) {
        int2 p0 = __ldg(&g_pair[j]);
        int2 p1 = __ldg(&g_pair[j + 1]);
        float4 v0 = __ldg(reinterpret_cast<const float4*>(hin + (size_t)p0.x * DD) + lane);
        float4 v1 = __ldg(reinterpret_cast<const float4*>(hin + (size_t)p1.x * DD) + lane);
        float n0 = __int_as_float(p0.y), n1 = __int_as_float(p1.y);
        acc.x = fmaf(n0, v0.x, acc.x); acc.y = fmaf(n0, v0.y, acc.y);
        acc.z = fmaf(n0, v0.z, acc.z); acc.w = fmaf(n0, v0.w, acc.w);
        acc.x = fmaf(n1, v1.x, acc.x); acc.y = fmaf(n1, v1.y, acc.y);
        acc.z = fmaf(n1, v1.z, acc.z); acc.w = fmaf(n1, v1.w, acc.w);
    }
    if (j < end) {
        int2 p0 = __ldg(&g_pair[j]);
        float4 v0 = __ldg(reinterpret_cast<const float4*>(hin + (size_t)p0.x * DD) + lane);
        float n0 = __int_as_float(p0.y);
        acc.x = fmaf(n0, v0.x, acc.x); acc.y = fmaf(n0, v0.y, acc.y);
        acc.z = fmaf(n0, v0.z, acc.z); acc.w = fmaf(n0, v0.w, acc.w);
    }
    reinterpret_cast<float4*>(hout + (size_t)node * DD)[lane] = acc;
}

// last layer fused with epilogue: out = AL*(x + h1 + h2 + acc), h2 == hin
__global__ void k_gather_last(const float* __restrict__ hin,
                              const float* __restrict__ x,
                              const float* __restrict__ h1,
                              float* __restrict__ out) {
    int gid = blockIdx.x * blockDim.x + threadIdx.x;
    int node = gid >> 4;
    if (node >= NN) return;
    int lane = gid & 15;
    int j = g_off[node];
    int end = g_off[node + 1];
    float4 acc = make_float4(0.f, 0.f, 0.f, 0.f);
    for (; j + 1 < end; j += 2) {
        int2 p0 = __ldg(&g_pair[j]);
        int2 p1 = __ldg(&g_pair[j + 1]);
        float4 v0 = __ldg(reinterpret_cast<const float4*>(hin + (size_t)p0.x * DD) + lane);
        float4 v1 = __ldg(reinterpret_cast<const float4*>(hin + (size_t)p1.x * DD) + lane);
        float n0 = __int_as_float(p0.y), n1 = __int_as_float(p1.y);
        acc.x = fmaf(n0, v0.x, acc.x); acc.y = fmaf(n0, v0.y, acc.y);
        acc.z = fmaf(n0, v0.z, acc.z); acc.w = fmaf(n0, v0.w, acc.w);
        acc.x = fmaf(n1, v1.x, acc.x); acc.y = fmaf(n1, v1.y, acc.y);
        acc.z = fmaf(n1, v1.z, acc.z); acc.w = fmaf(n1, v1.w, acc.w);
    }
    if (j < end) {
        int2 p0 = __ldg(&g_pair[j]);
        float4 v0 = __ldg(reinterpret_cast<const float4*>(hin + (size_t)p0.x * DD) + lane);
        float n0 = __int_as_float(p0.y);
        acc.x = fmaf(n0, v0.x, acc.x); acc.y = fmaf(n0, v0.y, acc.y);
        acc.z = fmaf(n0, v0.z, acc.z); acc.w = fmaf(n0, v0.w, acc.w);
    }
    size_t base = (size_t)node * DD;
    float4 a = __ldg(reinterpret_cast<const float4*>(x + base) + lane);
    float4 b = __ldg(reinterpret_cast<const float4*>(h1 + base) + lane);
    float4 c = __ldg(reinterpret_cast<const float4*>(hin + base) + lane);
    float4 o;
    o.x = AL * (a.x + b.x + c.x + acc.x);
    o.y = AL * (a.y + b.y + c.y + acc.y);
    o.z = AL * (a.z + b.z + c.z + acc.z);
    o.w = AL * (a.w + b.w + c.w + acc.w);
    reinterpret_cast<float4*>(out + base)[lane] = o;
}

// ---------------- launch ----------------
extern "C" void kernel_launch(void* const* d_in, const int* in_sizes, int n_in,
                              void* d_out, int out_size) {
    const float* x = (const float*)d_in[0];
    const float* attr = (const float*)d_in[1];
    const int* ei32 = (const int*)d_in[2];
    const unsigned char* m8 = (const unsigned char*)d_in[3];
    float* out = (float*)d_out;

    void* hbp = nullptr;
    cudaGetSymbolAddress(&hbp, g_hbuf);
    float* h1 = (float*)hbp;
    float* h2 = h1 + (size_t)NN * DD;

    const int B = 256;
    const int gridE = (EE + B - 1) / B;
    const int gridGather = (NN * 16 + B - 1) / B;

    k_probe<<<1, 1024>>>(ei32, m8);
    k_prep<<<gridE, B>>>(attr, ei32, m8);
    k_scan<<<NBLK, SCAN_B>>>();
    k_fill<<<gridE, B>>>();

    k_gather<<<gridGather, B>>>(x,  h1);
    k_gather<<<gridGather, B>>>(h1, h2);
    k_gather_last<<<gridGather, B>>>(h2, x, h1, out);
}

// round 8
// speedup vs baseline: 1.0889x; 1.0136x over previous
#include <cuda_runtime.h>
#include <stdint.h>

#define NN 100000
#define DD 64
#define EE 1200000
#define AL 0.25f
#define SCAN_B 1024
#define NBLK ((NN + SCAN_B - 1) / SCAN_B)   // 98
#define FIX (16777216.0f)                   // 2^24 fixed-point scale for degree

// ---------------- scratch (static __device__, zero-init at load) ----------------
__device__ unsigned long long g_cntdeg[NN];     // [63:40]=count, [39:0]=deg*2^24 ; self-cleaned by k_scan
__device__ __align__(16) float g_dinv[NN];
__device__ __align__(16) int4  g_edge[EE];      // (row, col, w bits, rank)
__device__ __align__(16) int2  g_pair[EE];      // (row, norm bits) grouped by target col
__device__ __align__(16) int   g_off[NN + 1];
__device__ int g_blk_status[NBLK];   // zeroed by k_prep block 0 each call
__device__ int g_blk_agg[NBLK];
__device__ int g_blk_pref[NBLK];
__device__ __align__(16) float g_hbuf[2][NN * DD];

// ---------------- kernels ----------------

// decode + materialize packed edge record + ONE packed 64-bit atomic giving
// weighted degree AND this edge's rank at its target node.
// Dtype detection is BLOCK-LOCAL on this block's own edges:
//  - edge_index viewed as int32: int64 storage (values < 2^31) -> every odd
//    word is 0; int32 storage -> odd words are real node indices
//    (P(==0) ~ 1e-5 each; 256 samples -> decision certain).
//  - mask viewed as bytes: int32-bool storage -> bytes at e%4!=0 are 0;
//    uint8 storage -> ~50% nonzero (192 samples -> certain).
// All probe reads are in-bounds under either interpretation.
__global__ void k_prep(const float* __restrict__ attr,
                       const int* __restrict__ ei32,
                       const unsigned char* __restrict__ m8) {
    int e = blockIdx.x * blockDim.x + threadIdx.x;
    int any_odd = 0, any_off = 0;
    if (e < EE) {
        any_odd = (ei32[2 * e + 1] != 0);
        unsigned char b = m8[e];
        if (e & 3) any_off = (b != 0);
    }
    bool idx32 = __syncthreads_or(any_odd);
    bool mask8 = __syncthreads_or(any_off);
    if (blockIdx.x == 0 && threadIdx.x < NBLK) g_blk_status[threadIdx.x] = 0;
    if (e >= EE) return;

    bool mk = mask8 ? (m8[e] != 0)
                    : (reinterpret_cast<const int*>(m8)[e] != 0);
    int r, c;
    if (idx32) { r = ei32[e];        c = ei32[EE + e]; }
    else       { r = ei32[2LL * e];  c = ei32[2LL * (EE + e)]; }
    float w = mk ? __ldg(attr + e) : 0.f;
    if ((unsigned)r >= NN || (unsigned)c >= NN) w = 0.f;
    int rk = 0;
    if (w > 0.f) {
        unsigned long long inc = (1ull << 40) | (unsigned long long)(w * FIX);
        unsigned long long old = atomicAdd(&g_cntdeg[c], inc);
        rk = (int)(old >> 40);
    }
    g_edge[e] = make_int4(r, c, __float_as_int(w), rk);
}

// fused: unpack (cnt,deg) -> dinv + exclusive scan of cnt (decoupled lookback)
// + self-clean cntdeg for the next graph replay
__global__ void __launch_bounds__(SCAN_B) k_scan() {
    __shared__ int s_wsum[32];
    __shared__ int s_bexcl;
    int b = blockIdx.x;
    int i = b * SCAN_B + threadIdx.x;
    int lane = threadIdx.x & 31;
    int wid = threadIdx.x >> 5;

    int v = 0;
    if (i < NN) {
        unsigned long long pk = g_cntdeg[i];
        g_cntdeg[i] = 0ull;          // self-clean
        v = (int)(pk >> 40);
        float d = (float)(pk & ((1ull << 40) - 1ull)) * (1.0f / FIX);
        g_dinv[i] = (d > 0.f) ? rsqrtf(d) : 0.f;
    }

    int x = v;
    #pragma unroll
    for (int d = 1; d < 32; d <<= 1) {
        int t = __shfl_up_sync(0xffffffffu, x, d);
        if (lane >= d) x += t;
    }
    if (lane == 31) s_wsum[wid] = x;
    __syncthreads();
    if (wid == 0) {
        int y = s_wsum[lane];
        #pragma unroll
        for (int d = 1; d < 32; d <<= 1) {
            int t = __shfl_up_sync(0xffffffffu, y, d);
            if (lane >= d) y += t;
        }
        s_wsum[lane] = y;
    }
    __syncthreads();
    int incl = x + (wid > 0 ? s_wsum[wid - 1] : 0);
    int agg = s_wsum[31];

    if (threadIdx.x == 0) {
        g_blk_agg[b] = agg;
        __threadfence();
        atomicExch(&g_blk_status[b], 1);
        int excl = 0;
        int p = b - 1;
        while (p >= 0) {
            int s;
            do { s = atomicAdd(&g_blk_status[p], 0); } while (s == 0);
            if (s == 2) { excl += *((volatile int*)&g_blk_pref[p]); break; }
            excl += *((volatile int*)&g_blk_agg[p]);
            p--;
        }
        g_blk_pref[b] = excl + agg;
        __threadfence();
        atomicExch(&g_blk_status[b], 2);
        s_bexcl = excl;
    }
    __syncthreads();
    int bexcl = s_bexcl;
    if (i < NN) {
        g_off[i] = bexcl + incl - v;
        if (i == NN - 1) g_off[NN] = bexcl + incl;
    }
}

// fill CSR, atomic-free, 4 edges/thread in phases for MLP.
// pos = off[col] + rank. (norm may be 0 if dinv[row]==0; contributes nothing)
#define FC 4
__global__ void k_fill() {
    int base = blockIdx.x * (blockDim.x * FC) + threadIdx.x;
    int4 ed[FC];
    #pragma unroll
    for (int k = 0; k < FC; k++) {
        int e = base + k * blockDim.x;
        ed[k] = (e < EE) ? g_edge[e] : make_int4(0, 0, 0, 0);
    }
    float dr[FC], dc[FC];
    int of[FC];
    #pragma unroll
    for (int k = 0; k < FC; k++) {
        if (__int_as_float(ed[k].z) > 0.f) {
            dr[k] = g_dinv[ed[k].x];
            dc[k] = g_dinv[ed[k].y];
            of[k] = g_off[ed[k].y];
        }
    }
    #pragma unroll
    for (int k = 0; k < FC; k++) {
        float w = __int_as_float(ed[k].z);
        if (w > 0.f) {
            g_pair[of[k] + ed[k].w] =
                make_int2(ed[k].x, __float_as_int(w * dr[k] * dc[k]));
        }
    }
}

// pull one layer: 16 threads/node, register accumulation, unroll x2
__global__ void k_gather(const float* __restrict__ hin, float* __restrict__ hout) {
    int gid = blockIdx.x * blockDim.x + threadIdx.x;
    int node = gid >> 4;
    if (node >= NN) return;
    int lane = gid & 15;
    int j = g_off[node];
    int end = g_off[node + 1];
    float4 acc = make_float4(0.f, 0.f, 0.f, 0.f);
    for (; j + 1 < end; j += 2) {
        int2 p0 = __ldg(&g_pair[j]);
        int2 p1 = __ldg(&g_pair[j + 1]);
        float4 v0 = __ldg(reinterpret_cast<const float4*>(hin + (size_t)p0.x * DD) + lane);
        float4 v1 = __ldg(reinterpret_cast<const float4*>(hin + (size_t)p1.x * DD) + lane);
        float n0 = __int_as_float(p0.y), n1 = __int_as_float(p1.y);
        acc.x = fmaf(n0, v0.x, acc.x); acc.y = fmaf(n0, v0.y, acc.y);
        acc.z = fmaf(n0, v0.z, acc.z); acc.w = fmaf(n0, v0.w, acc.w);
        acc.x = fmaf(n1, v1.x, acc.x); acc.y = fmaf(n1, v1.y, acc.y);
        acc.z = fmaf(n1, v1.z, acc.z); acc.w = fmaf(n1, v1.w, acc.w);
    }
    if (j < end) {
        int2 p0 = __ldg(&g_pair[j]);
        float4 v0 = __ldg(reinterpret_cast<const float4*>(hin + (size_t)p0.x * DD) + lane);
        float n0 = __int_as_float(p0.y);
        acc.x = fmaf(n0, v0.x, acc.x); acc.y = fmaf(n0, v0.y, acc.y);
        acc.z = fmaf(n0, v0.z, acc.z); acc.w = fmaf(n0, v0.w, acc.w);
    }
    reinterpret_cast<float4*>(hout + (size_t)node * DD)[lane] = acc;
}

// last layer fused with epilogue: out = AL*(x + h1 + h2 + acc), h2 == hin
__global__ void k_gather_last(const float* __restrict__ hin,
                              const float* __restrict__ x,
                              const float* __restrict__ h1,
                              float* __restrict__ out) {
    int gid = blockIdx.x * blockDim.x + threadIdx.x;
    int node = gid >> 4;
    if (node >= NN) return;
    int lane = gid & 15;
    int j = g_off[node];
    int end = g_off[node + 1];
    float4 acc = make_float4(0.f, 0.f, 0.f, 0.f);
    for (; j + 1 < end; j += 2) {
        int2 p0 = __ldg(&g_pair[j]);
        int2 p1 = __ldg(&g_pair[j + 1]);
        float4 v0 = __ldg(reinterpret_cast<const float4*>(hin + (size_t)p0.x * DD) + lane);
        float4 v1 = __ldg(reinterpret_cast<const float4*>(hin + (size_t)p1.x * DD) + lane);
        float n0 = __int_as_float(p0.y), n1 = __int_as_float(p1.y);
        acc.x = fmaf(n0, v0.x, acc.x); acc.y = fmaf(n0, v0.y, acc.y);
        acc.z = fmaf(n0, v0.z, acc.z); acc.w = fmaf(n0, v0.w, acc.w);
        acc.x = fmaf(n1, v1.x, acc.x); acc.y = fmaf(n1, v1.y, acc.y);
        acc.z = fmaf(n1, v1.z, acc.z); acc.w = fmaf(n1, v1.w, acc.w);
    }
    if (j < end) {
        int2 p0 = __ldg(&g_pair[j]);
        float4 v0 = __ldg(reinterpret_cast<const float4*>(hin + (size_t)p0.x * DD) + lane);
        float n0 = __int_as_float(p0.y);
        acc.x = fmaf(n0, v0.x, acc.x); acc.y = fmaf(n0, v0.y, acc.y);
        acc.z = fmaf(n0, v0.z, acc.z); acc.w = fmaf(n0, v0.w, acc.w);
    }
    size_t base = (size_t)node * DD;
    float4 a = __ldg(reinterpret_cast<const float4*>(x + base) + lane);
    float4 b = __ldg(reinterpret_cast<const float4*>(h1 + base) + lane);
    float4 c = __ldg(reinterpret_cast<const float4*>(hin + base) + lane);
    float4 o;
    o.x = AL * (a.x + b.x + c.x + acc.x);
    o.y = AL * (a.y + b.y + c.y + acc.y);
    o.z = AL * (a.z + b.z + c.z + acc.z);
    o.w = AL * (a.w + b.w + c.w + acc.w);
    reinterpret_cast<float4*>(out + base)[lane] = o;
}

// ---------------- launch ----------------
extern "C" void kernel_launch(void* const* d_in, const int* in_sizes, int n_in,
                              void* d_out, int out_size) {
    const float* x = (const float*)d_in[0];
    const float* attr = (const float*)d_in[1];
    const int* ei32 = (const int*)d_in[2];
    const unsigned char* m8 = (const unsigned char*)d_in[3];
    float* out = (float*)d_out;

    void* hbp = nullptr;
    cudaGetSymbolAddress(&hbp, g_hbuf);
    float* h1 = (float*)hbp;
    float* h2 = h1 + (size_t)NN * DD;

    const int B = 256;
    const int gridE = (EE + B - 1) / B;
    const int gridFill = (EE + B * FC - 1) / (B * FC);
    const int gridGather = (NN * 16 + B - 1) / B;

    k_prep<<<gridE, B>>>(attr, ei32, m8);
    k_scan<<<NBLK, SCAN_B>>>();
    k_fill<<<gridFill, B>>>();

    k_gather<<<gridGather, B>>>(x,  h1);
    k_gather<<<gridGather, B>>>(h1, h2);
    k_gather_last<<<gridGather, B>>>(h2, x, h1, out);
}